// round 7
// baseline (speedup 1.0000x reference)
#include <cuda_runtime.h>
#include <cuda_bf16.h>
#include <stdint.h>
#include <math.h>

#define Cdim   512
#define Tdim   8
#define HWdim  2304
#define Ndim   18432
#define Gdim   32
#define CPG    16
#define EPSv   1e-6f
#define SCALEv 0.044194173824159216f
#define CN     ((size_t)Cdim * Ndim)
#define SSZ    ((size_t)Tdim * HWdim * HWdim)
#define WSZ    (Cdim * Cdim)

// ---------------- scratch ----------------
__device__ float g_mean[Gdim];
__device__ float g_rstd[Gdim];
__device__ float g_s[SSZ];
__device__ __nv_bfloat16 g_hnh[CN], g_hnl[CN];
__device__ __nv_bfloat16 g_qkvh[3 * CN], g_qkvl[3 * CN];
__device__ __nv_bfloat16 g_ofh[CN], g_ofl[CN];
__device__ __nv_bfloat16 g_ph [SSZ], g_pl [SSZ];
__device__ __nv_bfloat16 g_wh[4 * WSZ], g_wl[4 * WSZ];

__device__ __forceinline__ void split_bf16(float x, __nv_bfloat16& h, __nv_bfloat16& l) {
    h = __float2bfloat16(x);
    l = __float2bfloat16(x - __bfloat162float(h));
}

// ---------------- weight split (all 4 matrices, grid.z selects) ----------------
__global__ void splitw_kernel(const float* __restrict__ w0, const float* __restrict__ w1,
                              const float* __restrict__ w2, const float* __restrict__ w3) {
    const int z = blockIdx.z;
    const float* w = (z == 0) ? w0 : (z == 1) ? w1 : (z == 2) ? w2 : w3;
    int i = (blockIdx.x * 256 + threadIdx.x) * 4;
    float4 v = *(const float4*)(w + i);
    __nv_bfloat16 h[4], l[4];
    split_bf16(v.x, h[0], l[0]); split_bf16(v.y, h[1], l[1]);
    split_bf16(v.z, h[2], l[2]); split_bf16(v.w, h[3], l[3]);
    __nv_bfloat16* oh = g_wh + z * WSZ;
    __nv_bfloat16* ol = g_wl + z * WSZ;
    *(__nv_bfloat162*)(oh + i)     = __nv_bfloat162(h[0], h[1]);
    *(__nv_bfloat162*)(oh + i + 2) = __nv_bfloat162(h[2], h[3]);
    *(__nv_bfloat162*)(ol + i)     = __nv_bfloat162(l[0], l[1]);
    *(__nv_bfloat162*)(ol + i + 2) = __nv_bfloat162(l[2], l[3]);
}

// ---------------- GroupNorm ----------------
__global__ void gn_stats_kernel(const float* __restrict__ x) {
    const int g = blockIdx.x;
    const float4* base = (const float4*)(x + (size_t)g * CPG * Ndim);
    const int n4 = (CPG * Ndim) / 4;
    float s = 0.f, ss = 0.f;
    for (int i = threadIdx.x; i < n4; i += blockDim.x) {
        float4 v = base[i];
        s  += v.x + v.y + v.z + v.w;
        ss += v.x*v.x + v.y*v.y + v.z*v.z + v.w*v.w;
    }
    __shared__ float sh1[1024];
    __shared__ float sh2[1024];
    sh1[threadIdx.x] = s; sh2[threadIdx.x] = ss;
    __syncthreads();
    for (int off = 512; off > 0; off >>= 1) {
        if (threadIdx.x < off) {
            sh1[threadIdx.x] += sh1[threadIdx.x + off];
            sh2[threadIdx.x] += sh2[threadIdx.x + off];
        }
        __syncthreads();
    }
    if (threadIdx.x == 0) {
        const float inv = 1.f / (float)(CPG * Ndim);
        float m = sh1[0] * inv;
        float var = sh2[0] * inv - m * m;
        g_mean[g] = m;
        g_rstd[g] = rsqrtf(var + EPSv);
    }
}

__global__ void gn_apply_kernel(const float* __restrict__ x,
                                const float* __restrict__ gamma,
                                const float* __restrict__ beta) {
    int i4 = blockIdx.x * blockDim.x + threadIdx.x;
    int c  = (i4 * 4) / Ndim;
    int g  = c >> 4;
    float r  = g_rstd[g];
    float ga = gamma[c] * r;
    float be = beta[c] - g_mean[g] * ga;
    float4 v = ((const float4*)x)[i4];
    float o[4] = {v.x*ga+be, v.y*ga+be, v.z*ga+be, v.w*ga+be};
    __nv_bfloat16 h[4], l[4];
#pragma unroll
    for (int j = 0; j < 4; j++) split_bf16(o[j], h[j], l[j]);
    size_t i = (size_t)i4 * 4;
    *(__nv_bfloat162*)(g_hnh + i)     = __nv_bfloat162(h[0], h[1]);
    *(__nv_bfloat162*)(g_hnh + i + 2) = __nv_bfloat162(h[2], h[3]);
    *(__nv_bfloat162*)(g_hnl + i)     = __nv_bfloat162(l[0], l[1]);
    *(__nv_bfloat162*)(g_hnl + i + 2) = __nv_bfloat162(l[2], l[3]);
}

// ---------------- PTX helpers ----------------
__device__ __forceinline__ uint32_t smem_u32(const void* p) {
    return (uint32_t)__cvta_generic_to_shared(p);
}
#define CP16(d,s) asm volatile("cp.async.cg.shared.global [%0], [%1], 16;" :: "r"(d), "l"(s))
#define CPCOMMIT() asm volatile("cp.async.commit_group;")
#define CPWAIT(n)  asm volatile("cp.async.wait_group %0;" :: "n"(n) : "memory")

#define LDMX4(r0,r1,r2,r3,addr) \
    asm volatile("ldmatrix.sync.aligned.m8n8.x4.shared.b16 {%0,%1,%2,%3}, [%4];" \
        : "=r"(r0),"=r"(r1),"=r"(r2),"=r"(r3) : "r"(addr))
#define LDMX4T(r0,r1,r2,r3,addr) \
    asm volatile("ldmatrix.sync.aligned.m8n8.x4.trans.shared.b16 {%0,%1,%2,%3}, [%4];" \
        : "=r"(r0),"=r"(r1),"=r"(r2),"=r"(r3) : "r"(addr))
#define LDMX2(r0,r1,addr) \
    asm volatile("ldmatrix.sync.aligned.m8n8.x2.shared.b16 {%0,%1}, [%2];" \
        : "=r"(r0),"=r"(r1) : "r"(addr))
#define LDMX2T(r0,r1,addr) \
    asm volatile("ldmatrix.sync.aligned.m8n8.x2.trans.shared.b16 {%0,%1}, [%2];" \
        : "=r"(r0),"=r"(r1) : "r"(addr))
#define MMA_B16(c0,c1,c2,c3,a0,a1,a2,a3,b0,b1) \
    asm volatile("mma.sync.aligned.m16n8k16.row.col.f32.bf16.bf16.f32 " \
        "{%0,%1,%2,%3}, {%4,%5,%6,%7}, {%8,%9}, {%0,%1,%2,%3};" \
        : "+f"(c0),"+f"(c1),"+f"(c2),"+f"(c3) \
        : "r"(a0),"r"(a1),"r"(a2),"r"(a3),"r"(b0),"r"(b1))

// Stage layout (halves): A_h[5120] A_l[5120] B_h[5120] B_l[5120]; 3 stages.
#define STG_H 20480
#define SMEMB (3 * STG_H * 2)   // 122880 bytes

// MODE 0: proj   A = weights hi/lo (z*WSZ offset), B=[512][Ndim]. SPLIT: out -> qkv[z]; else fp32+bias+resid
// MODE 1: scores A=q hi/lo [k][m] str Ndim, B=k hi/lo [k][n] str Ndim -> fp32 S * scale  (z = frame)
// MODE 2: pv     A=v hi/lo [m][k] str Ndim, B=P hi/lo [n][k] str HWdim -> split of       (z = frame)
template<int MODE, bool SPLIT>
__global__ void __launch_bounds__(256)
mma_gemm(const __nv_bfloat16* __restrict__ Agh, const __nv_bfloat16* __restrict__ Agl,
         const __nv_bfloat16* __restrict__ Bgh, const __nv_bfloat16* __restrict__ Bgl,
         const float* __restrict__ bias0, const float* __restrict__ bias1,
         const float* __restrict__ bias2, const float* __restrict__ resid,
         float* __restrict__ Cf, __nv_bfloat16* __restrict__ Ch, __nv_bfloat16* __restrict__ Cl)
{
    constexpr int KDIM = (MODE == 2) ? HWdim : Cdim;
    constexpr int NSTG = KDIM / 32;

    extern __shared__ __nv_bfloat16 sm[];

    const int tid  = threadIdx.x;
    const int lane = tid & 31;
    const int warp = tid >> 5;
    const int wm   = (warp >> 2) * 64;
    const int wn   = (warp & 3) * 32;
    const int bn   = blockIdx.x * 128;
    const int bm   = blockIdx.y * 128;
    const int z    = blockIdx.z;

    const __nv_bfloat16 *Aph, *Apl, *Bph, *Bpl;
    const float* bias = bias0;
    if (MODE == 0) {
        Aph = Agh + (size_t)z * WSZ; Apl = Agl + (size_t)z * WSZ;
        Bph = Bgh; Bpl = Bgl;
        bias = (z == 0) ? bias0 : (z == 1) ? bias1 : bias2;
    } else if (MODE == 1) {
        Aph = Agh + (size_t)z * HWdim; Apl = Agl + (size_t)z * HWdim;
        Bph = Bgh + (size_t)z * HWdim; Bpl = Bgl + (size_t)z * HWdim;
    } else {
        Aph = Agh + (size_t)z * HWdim; Apl = Agl + (size_t)z * HWdim;
        Bph = Bgh + (size_t)z * HWdim * HWdim; Bpl = Bgl + (size_t)z * HWdim * HWdim;
    }

    auto issue = [&](int buf, int k0) {
        __nv_bfloat16* Sa_h = sm + buf * STG_H;
        __nv_bfloat16* Sa_l = Sa_h + 5120;
        __nv_bfloat16* Sb_h = Sa_h + 10240;
        __nv_bfloat16* Sb_l = Sa_h + 15360;
        if (MODE == 1) {                       // A: [k][m] -> [32][136]
            int row = tid >> 3, c0 = (tid & 7) * 8;
            const __nv_bfloat16* s0 = Aph + (size_t)(k0 + row) * Ndim + bm;
            const __nv_bfloat16* s1 = Apl + (size_t)(k0 + row) * Ndim + bm;
            CP16(smem_u32(Sa_h + row*136 + c0),      s0 + c0);
            CP16(smem_u32(Sa_h + row*136 + c0 + 64), s0 + c0 + 64);
            CP16(smem_u32(Sa_l + row*136 + c0),      s1 + c0);
            CP16(smem_u32(Sa_l + row*136 + c0 + 64), s1 + c0 + 64);
        } else {                               // A: [m][k] -> [128][40]
            const size_t lda = (MODE == 0) ? (size_t)Cdim : (size_t)Ndim;
            int row = tid >> 1, c0 = (tid & 1) * 8;
            const __nv_bfloat16* s0 = Aph + (size_t)(bm + row) * lda + k0;
            const __nv_bfloat16* s1 = Apl + (size_t)(bm + row) * lda + k0;
            CP16(smem_u32(Sa_h + row*40 + c0),      s0 + c0);
            CP16(smem_u32(Sa_h + row*40 + c0 + 16), s0 + c0 + 16);
            CP16(smem_u32(Sa_l + row*40 + c0),      s1 + c0);
            CP16(smem_u32(Sa_l + row*40 + c0 + 16), s1 + c0 + 16);
        }
        if (MODE == 2) {                       // B: [n][k] -> [128][40]
            int row = tid >> 1, c0 = (tid & 1) * 8;
            const __nv_bfloat16* s0 = Bph + (size_t)(bn + row) * HWdim + k0;
            const __nv_bfloat16* s1 = Bpl + (size_t)(bn + row) * HWdim + k0;
            CP16(smem_u32(Sb_h + row*40 + c0),      s0 + c0);
            CP16(smem_u32(Sb_h + row*40 + c0 + 16), s0 + c0 + 16);
            CP16(smem_u32(Sb_l + row*40 + c0),      s1 + c0);
            CP16(smem_u32(Sb_l + row*40 + c0 + 16), s1 + c0 + 16);
        } else {                               // B: [k][n] -> [32][136]
            int row = tid >> 3, c0 = (tid & 7) * 8;
            const __nv_bfloat16* s0 = Bph + (size_t)(k0 + row) * Ndim + bn;
            const __nv_bfloat16* s1 = Bpl + (size_t)(k0 + row) * Ndim + bn;
            CP16(smem_u32(Sb_h + row*136 + c0),      s0 + c0);
            CP16(smem_u32(Sb_h + row*136 + c0 + 64), s0 + c0 + 64);
            CP16(smem_u32(Sb_l + row*136 + c0),      s1 + c0);
            CP16(smem_u32(Sb_l + row*136 + c0 + 64), s1 + c0 + 64);
        }
    };

    float acc[4][4][4] = {};

    issue(0, 0);  CPCOMMIT();
    issue(1, 32); CPCOMMIT();

    for (int s = 0; s < NSTG; s++) {
        if (s + 1 < NSTG) CPWAIT(1); else CPWAIT(0);
        __syncthreads();                       // stage s visible; buffer (s+2)%3 free
        if (s + 2 < NSTG) { issue((s + 2) % 3, (s + 2) * 32); CPCOMMIT(); }

        const __nv_bfloat16* Sa_h = sm + (s % 3) * STG_H;
        const __nv_bfloat16* Sa_l = Sa_h + 5120;
        const __nv_bfloat16* Sb_h = Sa_h + 10240;
        const __nv_bfloat16* Sb_l = Sa_h + 15360;

#pragma unroll
        for (int k16 = 0; k16 < 32; k16 += 16) {
            uint32_t a[4][4], bh[4][2], bl[4][2];
#pragma unroll
            for (int mi = 0; mi < 4; mi++) {
                if (MODE == 1) {
                    int row = k16 + (lane & 7) + ((lane >> 4) << 3);
                    int col = wm + mi*16 + (((lane >> 3) & 1) << 3);
                    LDMX4T(a[mi][0], a[mi][1], a[mi][2], a[mi][3],
                           smem_u32(Sa_h + row*136 + col));
                } else {
                    LDMX4(a[mi][0], a[mi][1], a[mi][2], a[mi][3],
                          smem_u32(Sa_h + (wm + mi*16 + (lane & 15))*40 + k16 + ((lane >> 4) << 3)));
                }
            }
#pragma unroll
            for (int ni = 0; ni < 4; ni++) {
                if (MODE == 2) {
                    uint32_t ad = smem_u32(Sb_h + (wn + ni*8 + (lane & 7))*40 + k16 + (((lane >> 3) & 1) << 3));
                    LDMX2(bh[ni][0], bh[ni][1], ad);
                    uint32_t ad2 = smem_u32(Sb_l + (wn + ni*8 + (lane & 7))*40 + k16 + (((lane >> 3) & 1) << 3));
                    LDMX2(bl[ni][0], bl[ni][1], ad2);
                } else {
                    uint32_t ad = smem_u32(Sb_h + (k16 + (lane & 15))*136 + wn + ni*8);
                    LDMX2T(bh[ni][0], bh[ni][1], ad);
                    uint32_t ad2 = smem_u32(Sb_l + (k16 + (lane & 15))*136 + wn + ni*8);
                    LDMX2T(bl[ni][0], bl[ni][1], ad2);
                }
            }
#pragma unroll
            for (int mi = 0; mi < 4; mi++)
#pragma unroll
                for (int ni = 0; ni < 4; ni++) {
                    MMA_B16(acc[mi][ni][0], acc[mi][ni][1], acc[mi][ni][2], acc[mi][ni][3],
                            a[mi][0], a[mi][1], a[mi][2], a[mi][3], bh[ni][0], bh[ni][1]);
                    MMA_B16(acc[mi][ni][0], acc[mi][ni][1], acc[mi][ni][2], acc[mi][ni][3],
                            a[mi][0], a[mi][1], a[mi][2], a[mi][3], bl[ni][0], bl[ni][1]);
                }
#pragma unroll
            for (int mi = 0; mi < 4; mi++) {
                if (MODE == 1) {
                    int row = k16 + (lane & 7) + ((lane >> 4) << 3);
                    int col = wm + mi*16 + (((lane >> 3) & 1) << 3);
                    LDMX4T(a[mi][0], a[mi][1], a[mi][2], a[mi][3],
                           smem_u32(Sa_l + row*136 + col));
                } else {
                    LDMX4(a[mi][0], a[mi][1], a[mi][2], a[mi][3],
                          smem_u32(Sa_l + (wm + mi*16 + (lane & 15))*40 + k16 + ((lane >> 4) << 3)));
                }
            }
#pragma unroll
            for (int mi = 0; mi < 4; mi++)
#pragma unroll
                for (int ni = 0; ni < 4; ni++)
                    MMA_B16(acc[mi][ni][0], acc[mi][ni][1], acc[mi][ni][2], acc[mi][ni][3],
                            a[mi][0], a[mi][1], a[mi][2], a[mi][3], bh[ni][0], bh[ni][1]);
        }
        __syncthreads();
    }

    // ---- epilogue ----
    const size_t ldc = (MODE == 1) ? (size_t)HWdim : (size_t)Ndim;
    float* Cpf = 0; __nv_bfloat16 *Cph = 0, *Cpl = 0;
    if (MODE == 1)      Cpf = Cf + (size_t)z * HWdim * HWdim;
    else if (MODE == 2) { Cph = Ch + (size_t)z * HWdim; Cpl = Cl + (size_t)z * HWdim; }
    else if (SPLIT)     { Cph = Ch + (size_t)z * CN; Cpl = Cl + (size_t)z * CN; }
    else                Cpf = Cf;

    const int r = lane >> 2, cc = (lane & 3) * 2;
#pragma unroll
    for (int mi = 0; mi < 4; mi++) {
        const int row0 = bm + wm + mi*16 + r;
        const int row1 = row0 + 8;
        float bi0 = 0.f, bi1 = 0.f;
        if (MODE == 0) { bi0 = bias[row0]; bi1 = bias[row1]; }
#pragma unroll
        for (int ni = 0; ni < 4; ni++) {
            const int col = bn + wn + ni*8 + cc;
            float v00 = acc[mi][ni][0], v01 = acc[mi][ni][1];
            float v10 = acc[mi][ni][2], v11 = acc[mi][ni][3];
            if (MODE == 0) { v00 += bi0; v01 += bi0; v10 += bi1; v11 += bi1; }
            if (MODE == 1) { v00 *= SCALEv; v01 *= SCALEv; v10 *= SCALEv; v11 *= SCALEv; }
            if (SPLIT) {
                __nv_bfloat16 h0,l0,h1,l1,h2,l2,h3,l3;
                split_bf16(v00,h0,l0); split_bf16(v01,h1,l1);
                split_bf16(v10,h2,l2); split_bf16(v11,h3,l3);
                *(__nv_bfloat162*)(Cph + (size_t)row0*ldc + col) = __nv_bfloat162(h0,h1);
                *(__nv_bfloat162*)(Cpl + (size_t)row0*ldc + col) = __nv_bfloat162(l0,l1);
                *(__nv_bfloat162*)(Cph + (size_t)row1*ldc + col) = __nv_bfloat162(h2,h3);
                *(__nv_bfloat162*)(Cpl + (size_t)row1*ldc + col) = __nv_bfloat162(l2,l3);
            } else {
                if (MODE == 0 && resid) {
                    float2 r0 = *(const float2*)(resid + (size_t)row0*ldc + col);
                    float2 r1 = *(const float2*)(resid + (size_t)row1*ldc + col);
                    v00 += r0.x; v01 += r0.y; v10 += r1.x; v11 += r1.y;
                }
                *(float2*)(Cpf + (size_t)row0*ldc + col) = make_float2(v00, v01);
                *(float2*)(Cpf + (size_t)row1*ldc + col) = make_float2(v10, v11);
            }
        }
    }
}

// ---------------- softmax: fp32 scores -> bf16 hi/lo probs ----------------
__global__ void __launch_bounds__(256)
softmax_kernel() {
    const size_t base = (size_t)blockIdx.x * HWdim;
    const float* row = g_s + base;
    const int tid = threadIdx.x;
    float r[9];
    float mx = -1e30f;
#pragma unroll
    for (int i = 0; i < 9; i++) {
        r[i] = row[tid + i * 256];
        mx = fmaxf(mx, r[i]);
    }
    __shared__ float sh[256];
    sh[tid] = mx;
    __syncthreads();
    for (int off = 128; off > 0; off >>= 1) {
        if (tid < off) sh[tid] = fmaxf(sh[tid], sh[tid + off]);
        __syncthreads();
    }
    mx = sh[0];
    __syncthreads();
    float s = 0.f;
#pragma unroll
    for (int i = 0; i < 9; i++) {
        r[i] = __expf(r[i] - mx);
        s += r[i];
    }
    sh[tid] = s;
    __syncthreads();
    for (int off = 128; off > 0; off >>= 1) {
        if (tid < off) sh[tid] += sh[tid + off];
        __syncthreads();
    }
    const float inv = 1.f / sh[0];
#pragma unroll
    for (int i = 0; i < 9; i++) {
        float p = r[i] * inv;
        __nv_bfloat16 h, l;
        split_bf16(p, h, l);
        g_ph[base + tid + i * 256] = h;
        g_pl[base + tid + i * 256] = l;
    }
}

// ---------------- launch ----------------
extern "C" void kernel_launch(void* const* d_in, const int* in_sizes, int n_in,
                              void* d_out, int out_size) {
    __nv_bfloat16 *p_hnh, *p_hnl, *p_qkvh, *p_qkvl, *p_ofh, *p_ofl, *p_ph, *p_pl, *p_wh, *p_wl;
    float* p_s;
    cudaGetSymbolAddress((void**)&p_hnh,  g_hnh);  cudaGetSymbolAddress((void**)&p_hnl,  g_hnl);
    cudaGetSymbolAddress((void**)&p_qkvh, g_qkvh); cudaGetSymbolAddress((void**)&p_qkvl, g_qkvl);
    cudaGetSymbolAddress((void**)&p_ofh,  g_ofh);  cudaGetSymbolAddress((void**)&p_ofl,  g_ofl);
    cudaGetSymbolAddress((void**)&p_ph,   g_ph);   cudaGetSymbolAddress((void**)&p_pl,   g_pl);
    cudaGetSymbolAddress((void**)&p_wh,   g_wh);   cudaGetSymbolAddress((void**)&p_wl,   g_wl);
    cudaGetSymbolAddress((void**)&p_s,    g_s);

    static bool attr_done = false;
    if (!attr_done) {
        cudaFuncSetAttribute(mma_gemm<0,true >, cudaFuncAttributeMaxDynamicSharedMemorySize, SMEMB);
        cudaFuncSetAttribute(mma_gemm<0,false>, cudaFuncAttributeMaxDynamicSharedMemorySize, SMEMB);
        cudaFuncSetAttribute(mma_gemm<1,false>, cudaFuncAttributeMaxDynamicSharedMemorySize, SMEMB);
        cudaFuncSetAttribute(mma_gemm<2,true >, cudaFuncAttributeMaxDynamicSharedMemorySize, SMEMB);
        attr_done = true;
    }

    const float* x     = (const float*)d_in[0];
    const float* gamma = (const float*)d_in[1];
    const float* beta  = (const float*)d_in[2];
    const float* wq    = (const float*)d_in[3];
    const float* bq    = (const float*)d_in[4];
    const float* wk    = (const float*)d_in[5];
    const float* bk    = (const float*)d_in[6];
    const float* wv    = (const float*)d_in[7];
    const float* bv    = (const float*)d_in[8];
    const float* wo    = (const float*)d_in[9];
    const float* bo    = (const float*)d_in[10];
    float* out = (float*)d_out;

    // 0. split all weights (one launch)
    dim3 gW(WSZ / 1024, 1, 4);
    splitw_kernel<<<gW, 256>>>(wq, wk, wv, wo);

    // 1. GroupNorm -> split hn
    gn_stats_kernel<<<Gdim, 1024>>>(x);
    gn_apply_kernel<<<(int)(CN / 4) / 256, 256>>>(x, gamma, beta);

    // 2. Q+K+V projections in one launch (grid.z = proj index)
    dim3 gQKV(Ndim / 128, Cdim / 128, 3);
    mma_gemm<0,true><<<gQKV, 256, SMEMB>>>(p_wh, p_wl, p_hnh, p_hnl,
                                           bq, bk, bv, 0, 0, p_qkvh, p_qkvl);

    // 3. scores
    dim3 gSc(HWdim / 128, HWdim / 128, Tdim);
    mma_gemm<1,false><<<gSc, 256, SMEMB>>>(p_qkvh + 0*CN, p_qkvl + 0*CN,
                                           p_qkvh + 1*CN, p_qkvl + 1*CN,
                                           0, 0, 0, 0, p_s, 0, 0);

    // 4. softmax -> split probs
    softmax_kernel<<<Tdim * HWdim, 256>>>();

    // 5. PV (split of)
    dim3 gPV(HWdim / 128, Cdim / 128, Tdim);
    mma_gemm<2,true><<<gPV, 256, SMEMB>>>(p_qkvh + 2*CN, p_qkvl + 2*CN, p_ph, p_pl,
                                          0, 0, 0, 0, 0, p_ofh, p_ofl);

    // 6. output projection + bias + residual
    dim3 gOut(Ndim / 128, Cdim / 128, 1);
    mma_gemm<0,false><<<gOut, 256, SMEMB>>>(p_wh + 3*WSZ, p_wl + 3*WSZ, p_ofh, p_ofl,
                                            bo, 0, 0, x, out, 0, 0);
}

// round 8
// speedup vs baseline: 1.0025x; 1.0025x over previous
#include <cuda_runtime.h>
#include <cuda_bf16.h>
#include <stdint.h>
#include <math.h>

#define Cdim   512
#define Tdim   8
#define HWdim  2304
#define Ndim   18432
#define Gdim   32
#define CPG    16
#define EPSv   1e-6f
#define SCALEv 0.044194173824159216f
#define CN     ((size_t)Cdim * Ndim)
#define SSZ    ((size_t)Tdim * HWdim * HWdim)
#define WSZ    (Cdim * Cdim)

// ---------------- scratch ----------------
__device__ float g_mean[Gdim];
__device__ float g_rstd[Gdim];
__device__ float g_s[SSZ];
__device__ __nv_bfloat16 g_hnh[CN], g_hnl[CN];
__device__ __nv_bfloat16 g_qkvh[3 * CN], g_qkvl[3 * CN];
__device__ __nv_bfloat16 g_ofh[CN], g_ofl[CN];
__device__ __nv_bfloat16 g_ph [SSZ], g_pl [SSZ];
__device__ __nv_bfloat16 g_wh[4 * WSZ], g_wl[4 * WSZ];

__device__ __forceinline__ void split_bf16(float x, __nv_bfloat16& h, __nv_bfloat16& l) {
    h = __float2bfloat16(x);
    l = __float2bfloat16(x - __bfloat162float(h));
}

// ---------------- weight split (all 4 matrices, grid.z selects) ----------------
__global__ void splitw_kernel(const float* __restrict__ w0, const float* __restrict__ w1,
                              const float* __restrict__ w2, const float* __restrict__ w3) {
    const int z = blockIdx.z;
    const float* w = (z == 0) ? w0 : (z == 1) ? w1 : (z == 2) ? w2 : w3;
    int i = (blockIdx.x * 256 + threadIdx.x) * 4;
    float4 v = *(const float4*)(w + i);
    __nv_bfloat16 h[4], l[4];
    split_bf16(v.x, h[0], l[0]); split_bf16(v.y, h[1], l[1]);
    split_bf16(v.z, h[2], l[2]); split_bf16(v.w, h[3], l[3]);
    __nv_bfloat16* oh = g_wh + z * WSZ;
    __nv_bfloat16* ol = g_wl + z * WSZ;
    *(__nv_bfloat162*)(oh + i)     = __nv_bfloat162(h[0], h[1]);
    *(__nv_bfloat162*)(oh + i + 2) = __nv_bfloat162(h[2], h[3]);
    *(__nv_bfloat162*)(ol + i)     = __nv_bfloat162(l[0], l[1]);
    *(__nv_bfloat162*)(ol + i + 2) = __nv_bfloat162(l[2], l[3]);
}

// ---------------- GroupNorm ----------------
__global__ void gn_stats_kernel(const float* __restrict__ x) {
    const int g = blockIdx.x;
    const float4* base = (const float4*)(x + (size_t)g * CPG * Ndim);
    const int n4 = (CPG * Ndim) / 4;
    float s = 0.f, ss = 0.f;
    for (int i = threadIdx.x; i < n4; i += blockDim.x) {
        float4 v = base[i];
        s  += v.x + v.y + v.z + v.w;
        ss += v.x*v.x + v.y*v.y + v.z*v.z + v.w*v.w;
    }
    __shared__ float sh1[1024];
    __shared__ float sh2[1024];
    sh1[threadIdx.x] = s; sh2[threadIdx.x] = ss;
    __syncthreads();
    for (int off = 512; off > 0; off >>= 1) {
        if (threadIdx.x < off) {
            sh1[threadIdx.x] += sh1[threadIdx.x + off];
            sh2[threadIdx.x] += sh2[threadIdx.x + off];
        }
        __syncthreads();
    }
    if (threadIdx.x == 0) {
        const float inv = 1.f / (float)(CPG * Ndim);
        float m = sh1[0] * inv;
        float var = sh2[0] * inv - m * m;
        g_mean[g] = m;
        g_rstd[g] = rsqrtf(var + EPSv);
    }
}

__global__ void gn_apply_kernel(const float* __restrict__ x,
                                const float* __restrict__ gamma,
                                const float* __restrict__ beta) {
    int i4 = blockIdx.x * blockDim.x + threadIdx.x;
    int c  = (i4 * 4) / Ndim;
    int g  = c >> 4;
    float r  = g_rstd[g];
    float ga = gamma[c] * r;
    float be = beta[c] - g_mean[g] * ga;
    float4 v = ((const float4*)x)[i4];
    float o[4] = {v.x*ga+be, v.y*ga+be, v.z*ga+be, v.w*ga+be};
    __nv_bfloat16 h[4], l[4];
#pragma unroll
    for (int j = 0; j < 4; j++) split_bf16(o[j], h[j], l[j]);
    size_t i = (size_t)i4 * 4;
    *(__nv_bfloat162*)(g_hnh + i)     = __nv_bfloat162(h[0], h[1]);
    *(__nv_bfloat162*)(g_hnh + i + 2) = __nv_bfloat162(h[2], h[3]);
    *(__nv_bfloat162*)(g_hnl + i)     = __nv_bfloat162(l[0], l[1]);
    *(__nv_bfloat162*)(g_hnl + i + 2) = __nv_bfloat162(l[2], l[3]);
}

// ---------------- PTX helpers ----------------
__device__ __forceinline__ uint32_t smem_u32(const void* p) {
    return (uint32_t)__cvta_generic_to_shared(p);
}
#define CP16(d,s) asm volatile("cp.async.cg.shared.global [%0], [%1], 16;" :: "r"(d), "l"(s))
#define CPCOMMIT() asm volatile("cp.async.commit_group;")
#define CPWAIT(n)  asm volatile("cp.async.wait_group %0;" :: "n"(n) : "memory")

#define LDMX4(r0,r1,r2,r3,addr) \
    asm volatile("ldmatrix.sync.aligned.m8n8.x4.shared.b16 {%0,%1,%2,%3}, [%4];" \
        : "=r"(r0),"=r"(r1),"=r"(r2),"=r"(r3) : "r"(addr))
#define LDMX4T(r0,r1,r2,r3,addr) \
    asm volatile("ldmatrix.sync.aligned.m8n8.x4.trans.shared.b16 {%0,%1,%2,%3}, [%4];" \
        : "=r"(r0),"=r"(r1),"=r"(r2),"=r"(r3) : "r"(addr))
#define LDMX2(r0,r1,addr) \
    asm volatile("ldmatrix.sync.aligned.m8n8.x2.shared.b16 {%0,%1}, [%2];" \
        : "=r"(r0),"=r"(r1) : "r"(addr))
#define LDMX2T(r0,r1,addr) \
    asm volatile("ldmatrix.sync.aligned.m8n8.x2.trans.shared.b16 {%0,%1}, [%2];" \
        : "=r"(r0),"=r"(r1) : "r"(addr))
#define MMA_B16(c0,c1,c2,c3,a0,a1,a2,a3,b0,b1) \
    asm volatile("mma.sync.aligned.m16n8k16.row.col.f32.bf16.bf16.f32 " \
        "{%0,%1,%2,%3}, {%4,%5,%6,%7}, {%8,%9}, {%0,%1,%2,%3};" \
        : "+f"(c0),"+f"(c1),"+f"(c2),"+f"(c3) \
        : "r"(a0),"r"(a1),"r"(a2),"r"(a3),"r"(b0),"r"(b1))

// Stage layout (halves): A_h[5120] A_l[5120] B_h[5120] B_l[5120]; 3 stages.
#define STG_H 20480
#define SMEMB (3 * STG_H * 2)   // 122880 bytes

// MODE 0: proj   A = weights hi/lo (z*WSZ offset), B=[512][Ndim]. SPLIT: out -> qkv[z]; else fp32+bias+resid
// MODE 1: scores A=q hi/lo [k][m] str Ndim, B=k hi/lo [k][n] str Ndim -> fp32 S * scale  (z = frame)
// MODE 2: pv     A=v hi/lo [m][k] str Ndim, B=P hi/lo [n][k] str HWdim -> split of       (z = frame)
template<int MODE, bool SPLIT>
__global__ void __launch_bounds__(256)
mma_gemm(const __nv_bfloat16* __restrict__ Agh, const __nv_bfloat16* __restrict__ Agl,
         const __nv_bfloat16* __restrict__ Bgh, const __nv_bfloat16* __restrict__ Bgl,
         const float* __restrict__ bias0, const float* __restrict__ bias1,
         const float* __restrict__ bias2, const float* __restrict__ resid,
         float* __restrict__ Cf, __nv_bfloat16* __restrict__ Ch, __nv_bfloat16* __restrict__ Cl)
{
    constexpr int KDIM = (MODE == 2) ? HWdim : Cdim;
    constexpr int NSTG = KDIM / 32;

    extern __shared__ __nv_bfloat16 sm[];

    const int tid  = threadIdx.x;
    const int lane = tid & 31;
    const int warp = tid >> 5;
    const int wm   = (warp >> 2) * 64;
    const int wn   = (warp & 3) * 32;
    const int bn   = blockIdx.x * 128;
    const int bm   = blockIdx.y * 128;
    const int z    = blockIdx.z;

    const __nv_bfloat16 *Aph, *Apl, *Bph, *Bpl;
    const float* bias = bias0;
    if (MODE == 0) {
        Aph = Agh + (size_t)z * WSZ; Apl = Agl + (size_t)z * WSZ;
        Bph = Bgh; Bpl = Bgl;
        bias = (z == 0) ? bias0 : (z == 1) ? bias1 : bias2;
    } else if (MODE == 1) {
        Aph = Agh + (size_t)z * HWdim; Apl = Agl + (size_t)z * HWdim;
        Bph = Bgh + (size_t)z * HWdim; Bpl = Bgl + (size_t)z * HWdim;
    } else {
        Aph = Agh + (size_t)z * HWdim; Apl = Agl + (size_t)z * HWdim;
        Bph = Bgh + (size_t)z * HWdim * HWdim; Bpl = Bgl + (size_t)z * HWdim * HWdim;
    }

    auto issue = [&](int buf, int k0) {
        __nv_bfloat16* Sa_h = sm + buf * STG_H;
        __nv_bfloat16* Sa_l = Sa_h + 5120;
        __nv_bfloat16* Sb_h = Sa_h + 10240;
        __nv_bfloat16* Sb_l = Sa_h + 15360;
        if (MODE == 1) {                       // A: [k][m] -> [32][136]
            int row = tid >> 3, c0 = (tid & 7) * 8;
            const __nv_bfloat16* s0 = Aph + (size_t)(k0 + row) * Ndim + bm;
            const __nv_bfloat16* s1 = Apl + (size_t)(k0 + row) * Ndim + bm;
            CP16(smem_u32(Sa_h + row*136 + c0),      s0 + c0);
            CP16(smem_u32(Sa_h + row*136 + c0 + 64), s0 + c0 + 64);
            CP16(smem_u32(Sa_l + row*136 + c0),      s1 + c0);
            CP16(smem_u32(Sa_l + row*136 + c0 + 64), s1 + c0 + 64);
        } else {                               // A: [m][k] -> [128][40]
            const size_t lda = (MODE == 0) ? (size_t)Cdim : (size_t)Ndim;
            int row = tid >> 1, c0 = (tid & 1) * 8;
            const __nv_bfloat16* s0 = Aph + (size_t)(bm + row) * lda + k0;
            const __nv_bfloat16* s1 = Apl + (size_t)(bm + row) * lda + k0;
            CP16(smem_u32(Sa_h + row*40 + c0),      s0 + c0);
            CP16(smem_u32(Sa_h + row*40 + c0 + 16), s0 + c0 + 16);
            CP16(smem_u32(Sa_l + row*40 + c0),      s1 + c0);
            CP16(smem_u32(Sa_l + row*40 + c0 + 16), s1 + c0 + 16);
        }
        if (MODE == 2) {                       // B: [n][k] -> [128][40]
            int row = tid >> 1, c0 = (tid & 1) * 8;
            const __nv_bfloat16* s0 = Bph + (size_t)(bn + row) * HWdim + k0;
            const __nv_bfloat16* s1 = Bpl + (size_t)(bn + row) * HWdim + k0;
            CP16(smem_u32(Sb_h + row*40 + c0),      s0 + c0);
            CP16(smem_u32(Sb_h + row*40 + c0 + 16), s0 + c0 + 16);
            CP16(smem_u32(Sb_l + row*40 + c0),      s1 + c0);
            CP16(smem_u32(Sb_l + row*40 + c0 + 16), s1 + c0 + 16);
        } else {                               // B: [k][n] -> [32][136]
            int row = tid >> 3, c0 = (tid & 7) * 8;
            const __nv_bfloat16* s0 = Bph + (size_t)(k0 + row) * Ndim + bn;
            const __nv_bfloat16* s1 = Bpl + (size_t)(k0 + row) * Ndim + bn;
            CP16(smem_u32(Sb_h + row*136 + c0),      s0 + c0);
            CP16(smem_u32(Sb_h + row*136 + c0 + 64), s0 + c0 + 64);
            CP16(smem_u32(Sb_l + row*136 + c0),      s1 + c0);
            CP16(smem_u32(Sb_l + row*136 + c0 + 64), s1 + c0 + 64);
        }
    };

    float acc[4][4][4] = {};

    issue(0, 0);  CPCOMMIT();
    issue(1, 32); CPCOMMIT();

    for (int s = 0; s < NSTG; s++) {
        if (s + 1 < NSTG) CPWAIT(1); else CPWAIT(0);
        __syncthreads();                       // stage s visible; buffer (s+2)%3 free
        if (s + 2 < NSTG) { issue((s + 2) % 3, (s + 2) * 32); CPCOMMIT(); }

        const __nv_bfloat16* Sa_h = sm + (s % 3) * STG_H;
        const __nv_bfloat16* Sa_l = Sa_h + 5120;
        const __nv_bfloat16* Sb_h = Sa_h + 10240;
        const __nv_bfloat16* Sb_l = Sa_h + 15360;

#pragma unroll
        for (int k16 = 0; k16 < 32; k16 += 16) {
            uint32_t a[4][4], bh[4][2], bl[4][2];
#pragma unroll
            for (int mi = 0; mi < 4; mi++) {
                if (MODE == 1) {
                    int row = k16 + (lane & 7) + ((lane >> 4) << 3);
                    int col = wm + mi*16 + (((lane >> 3) & 1) << 3);
                    LDMX4T(a[mi][0], a[mi][1], a[mi][2], a[mi][3],
                           smem_u32(Sa_h + row*136 + col));
                } else {
                    LDMX4(a[mi][0], a[mi][1], a[mi][2], a[mi][3],
                          smem_u32(Sa_h + (wm + mi*16 + (lane & 15))*40 + k16 + ((lane >> 4) << 3)));
                }
            }
#pragma unroll
            for (int ni = 0; ni < 4; ni++) {
                if (MODE == 2) {
                    uint32_t ad = smem_u32(Sb_h + (wn + ni*8 + (lane & 7))*40 + k16 + (((lane >> 3) & 1) << 3));
                    LDMX2(bh[ni][0], bh[ni][1], ad);
                    uint32_t ad2 = smem_u32(Sb_l + (wn + ni*8 + (lane & 7))*40 + k16 + (((lane >> 3) & 1) << 3));
                    LDMX2(bl[ni][0], bl[ni][1], ad2);
                } else {
                    uint32_t ad = smem_u32(Sb_h + (k16 + (lane & 15))*136 + wn + ni*8);
                    LDMX2T(bh[ni][0], bh[ni][1], ad);
                    uint32_t ad2 = smem_u32(Sb_l + (k16 + (lane & 15))*136 + wn + ni*8);
                    LDMX2T(bl[ni][0], bl[ni][1], ad2);
                }
            }
#pragma unroll
            for (int mi = 0; mi < 4; mi++)
#pragma unroll
                for (int ni = 0; ni < 4; ni++) {
                    MMA_B16(acc[mi][ni][0], acc[mi][ni][1], acc[mi][ni][2], acc[mi][ni][3],
                            a[mi][0], a[mi][1], a[mi][2], a[mi][3], bh[ni][0], bh[ni][1]);
                    MMA_B16(acc[mi][ni][0], acc[mi][ni][1], acc[mi][ni][2], acc[mi][ni][3],
                            a[mi][0], a[mi][1], a[mi][2], a[mi][3], bl[ni][0], bl[ni][1]);
                }
#pragma unroll
            for (int mi = 0; mi < 4; mi++) {
                if (MODE == 1) {
                    int row = k16 + (lane & 7) + ((lane >> 4) << 3);
                    int col = wm + mi*16 + (((lane >> 3) & 1) << 3);
                    LDMX4T(a[mi][0], a[mi][1], a[mi][2], a[mi][3],
                           smem_u32(Sa_l + row*136 + col));
                } else {
                    LDMX4(a[mi][0], a[mi][1], a[mi][2], a[mi][3],
                          smem_u32(Sa_l + (wm + mi*16 + (lane & 15))*40 + k16 + ((lane >> 4) << 3)));
                }
            }
#pragma unroll
            for (int mi = 0; mi < 4; mi++)
#pragma unroll
                for (int ni = 0; ni < 4; ni++)
                    MMA_B16(acc[mi][ni][0], acc[mi][ni][1], acc[mi][ni][2], acc[mi][ni][3],
                            a[mi][0], a[mi][1], a[mi][2], a[mi][3], bh[ni][0], bh[ni][1]);
        }
        __syncthreads();
    }

    // ---- epilogue ----
    const size_t ldc = (MODE == 1) ? (size_t)HWdim : (size_t)Ndim;
    float* Cpf = 0; __nv_bfloat16 *Cph = 0, *Cpl = 0;
    if (MODE == 1)      Cpf = Cf + (size_t)z * HWdim * HWdim;
    else if (MODE == 2) { Cph = Ch + (size_t)z * HWdim; Cpl = Cl + (size_t)z * HWdim; }
    else if (SPLIT)     { Cph = Ch + (size_t)z * CN; Cpl = Cl + (size_t)z * CN; }
    else                Cpf = Cf;

    const int r = lane >> 2, cc = (lane & 3) * 2;
#pragma unroll
    for (int mi = 0; mi < 4; mi++) {
        const int row0 = bm + wm + mi*16 + r;
        const int row1 = row0 + 8;
        float bi0 = 0.f, bi1 = 0.f;
        if (MODE == 0) { bi0 = bias[row0]; bi1 = bias[row1]; }
#pragma unroll
        for (int ni = 0; ni < 4; ni++) {
            const int col = bn + wn + ni*8 + cc;
            float v00 = acc[mi][ni][0], v01 = acc[mi][ni][1];
            float v10 = acc[mi][ni][2], v11 = acc[mi][ni][3];
            if (MODE == 0) { v00 += bi0; v01 += bi0; v10 += bi1; v11 += bi1; }
            if (MODE == 1) { v00 *= SCALEv; v01 *= SCALEv; v10 *= SCALEv; v11 *= SCALEv; }
            if (SPLIT) {
                __nv_bfloat16 h0,l0,h1,l1,h2,l2,h3,l3;
                split_bf16(v00,h0,l0); split_bf16(v01,h1,l1);
                split_bf16(v10,h2,l2); split_bf16(v11,h3,l3);
                *(__nv_bfloat162*)(Cph + (size_t)row0*ldc + col) = __nv_bfloat162(h0,h1);
                *(__nv_bfloat162*)(Cpl + (size_t)row0*ldc + col) = __nv_bfloat162(l0,l1);
                *(__nv_bfloat162*)(Cph + (size_t)row1*ldc + col) = __nv_bfloat162(h2,h3);
                *(__nv_bfloat162*)(Cpl + (size_t)row1*ldc + col) = __nv_bfloat162(l2,l3);
            } else {
                if (MODE == 0 && resid) {
                    float2 r0 = *(const float2*)(resid + (size_t)row0*ldc + col);
                    float2 r1 = *(const float2*)(resid + (size_t)row1*ldc + col);
                    v00 += r0.x; v01 += r0.y; v10 += r1.x; v11 += r1.y;
                }
                *(float2*)(Cpf + (size_t)row0*ldc + col) = make_float2(v00, v01);
                *(float2*)(Cpf + (size_t)row1*ldc + col) = make_float2(v10, v11);
            }
        }
    }
}

// ---------------- softmax: fp32 scores -> bf16 hi/lo probs ----------------
__global__ void __launch_bounds__(256)
softmax_kernel() {
    const size_t base = (size_t)blockIdx.x * HWdim;
    const float* row = g_s + base;
    const int tid = threadIdx.x;
    float r[9];
    float mx = -1e30f;
#pragma unroll
    for (int i = 0; i < 9; i++) {
        r[i] = row[tid + i * 256];
        mx = fmaxf(mx, r[i]);
    }
    __shared__ float sh[256];
    sh[tid] = mx;
    __syncthreads();
    for (int off = 128; off > 0; off >>= 1) {
        if (tid < off) sh[tid] = fmaxf(sh[tid], sh[tid + off]);
        __syncthreads();
    }
    mx = sh[0];
    __syncthreads();
    float s = 0.f;
#pragma unroll
    for (int i = 0; i < 9; i++) {
        r[i] = __expf(r[i] - mx);
        s += r[i];
    }
    sh[tid] = s;
    __syncthreads();
    for (int off = 128; off > 0; off >>= 1) {
        if (tid < off) sh[tid] += sh[tid + off];
        __syncthreads();
    }
    const float inv = 1.f / sh[0];
#pragma unroll
    for (int i = 0; i < 9; i++) {
        float p = r[i] * inv;
        __nv_bfloat16 h, l;
        split_bf16(p, h, l);
        g_ph[base + tid + i * 256] = h;
        g_pl[base + tid + i * 256] = l;
    }
}

// ---------------- launch ----------------
extern "C" void kernel_launch(void* const* d_in, const int* in_sizes, int n_in,
                              void* d_out, int out_size) {
    __nv_bfloat16 *p_hnh, *p_hnl, *p_qkvh, *p_qkvl, *p_ofh, *p_ofl, *p_ph, *p_pl, *p_wh, *p_wl;
    float* p_s;
    cudaGetSymbolAddress((void**)&p_hnh,  g_hnh);  cudaGetSymbolAddress((void**)&p_hnl,  g_hnl);
    cudaGetSymbolAddress((void**)&p_qkvh, g_qkvh); cudaGetSymbolAddress((void**)&p_qkvl, g_qkvl);
    cudaGetSymbolAddress((void**)&p_ofh,  g_ofh);  cudaGetSymbolAddress((void**)&p_ofl,  g_ofl);
    cudaGetSymbolAddress((void**)&p_ph,   g_ph);   cudaGetSymbolAddress((void**)&p_pl,   g_pl);
    cudaGetSymbolAddress((void**)&p_wh,   g_wh);   cudaGetSymbolAddress((void**)&p_wl,   g_wl);
    cudaGetSymbolAddress((void**)&p_s,    g_s);

    static bool attr_done = false;
    if (!attr_done) {
        cudaFuncSetAttribute(mma_gemm<0,true >, cudaFuncAttributeMaxDynamicSharedMemorySize, SMEMB);
        cudaFuncSetAttribute(mma_gemm<0,false>, cudaFuncAttributeMaxDynamicSharedMemorySize, SMEMB);
        cudaFuncSetAttribute(mma_gemm<1,false>, cudaFuncAttributeMaxDynamicSharedMemorySize, SMEMB);
        cudaFuncSetAttribute(mma_gemm<2,true >, cudaFuncAttributeMaxDynamicSharedMemorySize, SMEMB);
        attr_done = true;
    }

    const float* x     = (const float*)d_in[0];
    const float* gamma = (const float*)d_in[1];
    const float* beta  = (const float*)d_in[2];
    const float* wq    = (const float*)d_in[3];
    const float* bq    = (const float*)d_in[4];
    const float* wk    = (const float*)d_in[5];
    const float* bk    = (const float*)d_in[6];
    const float* wv    = (const float*)d_in[7];
    const float* bv    = (const float*)d_in[8];
    const float* wo    = (const float*)d_in[9];
    const float* bo    = (const float*)d_in[10];
    float* out = (float*)d_out;

    // 0. split all weights (one launch)
    dim3 gW(WSZ / 1024, 1, 4);
    splitw_kernel<<<gW, 256>>>(wq, wk, wv, wo);

    // 1. GroupNorm -> split hn
    gn_stats_kernel<<<Gdim, 1024>>>(x);
    gn_apply_kernel<<<(int)(CN / 4) / 256, 256>>>(x, gamma, beta);

    // 2. Q+K+V projections in one launch (grid.z = proj index)
    dim3 gQKV(Ndim / 128, Cdim / 128, 3);
    mma_gemm<0,true><<<gQKV, 256, SMEMB>>>(p_wh, p_wl, p_hnh, p_hnl,
                                           bq, bk, bv, 0, 0, p_qkvh, p_qkvl);

    // 3. scores
    dim3 gSc(HWdim / 128, HWdim / 128, Tdim);
    mma_gemm<1,false><<<gSc, 256, SMEMB>>>(p_qkvh + 0*CN, p_qkvl + 0*CN,
                                           p_qkvh + 1*CN, p_qkvl + 1*CN,
                                           0, 0, 0, 0, p_s, 0, 0);

    // 4. softmax -> split probs
    softmax_kernel<<<Tdim * HWdim, 256>>>();

    // 5. PV (split of)
    dim3 gPV(HWdim / 128, Cdim / 128, Tdim);
    mma_gemm<2,true><<<gPV, 256, SMEMB>>>(p_qkvh + 2*CN, p_qkvl + 2*CN, p_ph, p_pl,
                                          0, 0, 0, 0, 0, p_ofh, p_ofl);

    // 6. output projection + bias + residual
    dim3 gOut(Ndim / 128, Cdim / 128, 1);
    mma_gemm<0,false><<<gOut, 256, SMEMB>>>(p_wh + 3*WSZ, p_wl + 3*WSZ, p_ofh, p_ofl,
                                            bo, 0, 0, x, out, 0, 0);
}

// round 9
// speedup vs baseline: 1.1641x; 1.1612x over previous
#include <cuda_runtime.h>
#include <cuda_bf16.h>
#include <stdint.h>
#include <math.h>

#define Cdim   512
#define Tdim   8
#define HWdim  2304
#define Ndim   18432
#define Gdim   32
#define CPG    16
#define EPSv   1e-6f
#define SCALEv 0.044194173824159216f
#define CN     ((size_t)Cdim * Ndim)
#define SSZ    ((size_t)Tdim * HWdim * HWdim)
#define WSZ    (Cdim * Cdim)

// ---------------- scratch ----------------
__device__ float g_mean[Gdim];
__device__ float g_rstd[Gdim];
__device__ float g_s[SSZ];
__device__ __nv_bfloat16 g_hnh[CN], g_hnl[CN];
__device__ __nv_bfloat16 g_qh [CN], g_ql [CN];
__device__ __nv_bfloat16 g_kh [CN], g_kl [CN];
__device__ __nv_bfloat16 g_vh [CN], g_vl [CN];
__device__ __nv_bfloat16 g_ofh[CN], g_ofl[CN];
__device__ __nv_bfloat16 g_ph [SSZ], g_pl [SSZ];
__device__ __nv_bfloat16 g_wh[4 * WSZ], g_wl[4 * WSZ];

__device__ __forceinline__ void split_bf16(float x, __nv_bfloat16& h, __nv_bfloat16& l) {
    h = __float2bfloat16(x);
    l = __float2bfloat16(x - __bfloat162float(h));
}

// ---------------- weight split (all 4 matrices, grid.z selects) ----------------
__global__ void splitw_kernel(const float* __restrict__ w0, const float* __restrict__ w1,
                              const float* __restrict__ w2, const float* __restrict__ w3) {
    const int z = blockIdx.z;
    const float* w = (z == 0) ? w0 : (z == 1) ? w1 : (z == 2) ? w2 : w3;
    int i = (blockIdx.x * 256 + threadIdx.x) * 4;
    float4 v = *(const float4*)(w + i);
    __nv_bfloat16 h[4], l[4];
    split_bf16(v.x, h[0], l[0]); split_bf16(v.y, h[1], l[1]);
    split_bf16(v.z, h[2], l[2]); split_bf16(v.w, h[3], l[3]);
    __nv_bfloat16* oh = g_wh + z * WSZ;
    __nv_bfloat16* ol = g_wl + z * WSZ;
    *(__nv_bfloat162*)(oh + i)     = __nv_bfloat162(h[0], h[1]);
    *(__nv_bfloat162*)(oh + i + 2) = __nv_bfloat162(h[2], h[3]);
    *(__nv_bfloat162*)(ol + i)     = __nv_bfloat162(l[0], l[1]);
    *(__nv_bfloat162*)(ol + i + 2) = __nv_bfloat162(l[2], l[3]);
}

// ---------------- GroupNorm ----------------
__global__ void gn_stats_kernel(const float* __restrict__ x) {
    const int g = blockIdx.x;
    const float4* base = (const float4*)(x + (size_t)g * CPG * Ndim);
    const int n4 = (CPG * Ndim) / 4;
    float s = 0.f, ss = 0.f;
    for (int i = threadIdx.x; i < n4; i += blockDim.x) {
        float4 v = base[i];
        s  += v.x + v.y + v.z + v.w;
        ss += v.x*v.x + v.y*v.y + v.z*v.z + v.w*v.w;
    }
    __shared__ float sh1[1024];
    __shared__ float sh2[1024];
    sh1[threadIdx.x] = s; sh2[threadIdx.x] = ss;
    __syncthreads();
    for (int off = 512; off > 0; off >>= 1) {
        if (threadIdx.x < off) {
            sh1[threadIdx.x] += sh1[threadIdx.x + off];
            sh2[threadIdx.x] += sh2[threadIdx.x + off];
        }
        __syncthreads();
    }
    if (threadIdx.x == 0) {
        const float inv = 1.f / (float)(CPG * Ndim);
        float m = sh1[0] * inv;
        float var = sh2[0] * inv - m * m;
        g_mean[g] = m;
        g_rstd[g] = rsqrtf(var + EPSv);
    }
}

__global__ void gn_apply_kernel(const float* __restrict__ x,
                                const float* __restrict__ gamma,
                                const float* __restrict__ beta) {
    int i4 = blockIdx.x * blockDim.x + threadIdx.x;
    int c  = (i4 * 4) / Ndim;
    int g  = c >> 4;
    float r  = g_rstd[g];
    float ga = gamma[c] * r;
    float be = beta[c] - g_mean[g] * ga;
    float4 v = ((const float4*)x)[i4];
    float o[4] = {v.x*ga+be, v.y*ga+be, v.z*ga+be, v.w*ga+be};
    __nv_bfloat16 h[4], l[4];
#pragma unroll
    for (int j = 0; j < 4; j++) split_bf16(o[j], h[j], l[j]);
    size_t i = (size_t)i4 * 4;
    *(__nv_bfloat162*)(g_hnh + i)     = __nv_bfloat162(h[0], h[1]);
    *(__nv_bfloat162*)(g_hnh + i + 2) = __nv_bfloat162(h[2], h[3]);
    *(__nv_bfloat162*)(g_hnl + i)     = __nv_bfloat162(l[0], l[1]);
    *(__nv_bfloat162*)(g_hnl + i + 2) = __nv_bfloat162(l[2], l[3]);
}

// ---------------- PTX helpers ----------------
__device__ __forceinline__ uint32_t smem_u32(const void* p) {
    return (uint32_t)__cvta_generic_to_shared(p);
}
#define CP16(d,s) asm volatile("cp.async.cg.shared.global [%0], [%1], 16;" :: "r"(d), "l"(s))
#define CPCOMMIT() asm volatile("cp.async.commit_group;")
#define CPWAIT(n)  asm volatile("cp.async.wait_group %0;" :: "n"(n) : "memory")

#define LDMX4(r0,r1,r2,r3,addr) \
    asm volatile("ldmatrix.sync.aligned.m8n8.x4.shared.b16 {%0,%1,%2,%3}, [%4];" \
        : "=r"(r0),"=r"(r1),"=r"(r2),"=r"(r3) : "r"(addr))
#define LDMX4T(r0,r1,r2,r3,addr) \
    asm volatile("ldmatrix.sync.aligned.m8n8.x4.trans.shared.b16 {%0,%1,%2,%3}, [%4];" \
        : "=r"(r0),"=r"(r1),"=r"(r2),"=r"(r3) : "r"(addr))
#define LDMX2(r0,r1,addr) \
    asm volatile("ldmatrix.sync.aligned.m8n8.x2.shared.b16 {%0,%1}, [%2];" \
        : "=r"(r0),"=r"(r1) : "r"(addr))
#define LDMX2T(r0,r1,addr) \
    asm volatile("ldmatrix.sync.aligned.m8n8.x2.trans.shared.b16 {%0,%1}, [%2];" \
        : "=r"(r0),"=r"(r1) : "r"(addr))
#define MMA_B16(c0,c1,c2,c3,a0,a1,a2,a3,b0,b1) \
    asm volatile("mma.sync.aligned.m16n8k16.row.col.f32.bf16.bf16.f32 " \
        "{%0,%1,%2,%3}, {%4,%5,%6,%7}, {%8,%9}, {%0,%1,%2,%3};" \
        : "+f"(c0),"+f"(c1),"+f"(c2),"+f"(c3) \
        : "r"(a0),"r"(a1),"r"(a2),"r"(a3),"r"(b0),"r"(b1))

// Stage layout (halves): A_h[5120] A_l[5120] B_h[5120] B_l[5120]; 2 stages.
#define STG_H 20480
#define SMEMB (2 * STG_H * 2)   // 81920 bytes -> 2 CTAs/SM fit

// MODE 0: proj   A=weights hi/lo [512][512], B=[512][Ndim]           -> split out or fp32(+bias+resid)
// MODE 1: scores A=q hi/lo [k][m] str Ndim,  B=k hi/lo [k][n] str Ndim -> fp32 S * scale
// MODE 2: pv     A=v hi/lo [m][k] str Ndim,  B=P hi/lo [n][k] str HWdim -> split of
template<int MODE, bool SPLIT>
__global__ void __launch_bounds__(256, 2)
mma_gemm(const __nv_bfloat16* __restrict__ Agh, const __nv_bfloat16* __restrict__ Agl,
         const __nv_bfloat16* __restrict__ Bgh, const __nv_bfloat16* __restrict__ Bgl,
         const float* __restrict__ bias, const float* __restrict__ resid,
         float* __restrict__ Cf, __nv_bfloat16* __restrict__ Ch, __nv_bfloat16* __restrict__ Cl)
{
    constexpr int KDIM = (MODE == 2) ? HWdim : Cdim;
    constexpr int NSTG = KDIM / 32;

    extern __shared__ __nv_bfloat16 sm[];

    const int tid  = threadIdx.x;
    const int lane = tid & 31;
    const int warp = tid >> 5;
    const int wm   = (warp >> 2) * 64;
    const int wn   = (warp & 3) * 32;
    const int bn   = blockIdx.x * 128;
    const int bm   = blockIdx.y * 128;
    const int f    = (MODE == 0) ? 0 : blockIdx.z;

    const __nv_bfloat16 *Aph, *Apl, *Bph, *Bpl;
    if (MODE == 0)      { Aph = Agh; Apl = Agl; Bph = Bgh; Bpl = Bgl; }
    else if (MODE == 1) { Aph = Agh + (size_t)f * HWdim; Apl = Agl + (size_t)f * HWdim;
                          Bph = Bgh + (size_t)f * HWdim; Bpl = Bgl + (size_t)f * HWdim; }
    else                { Aph = Agh + (size_t)f * HWdim; Apl = Agl + (size_t)f * HWdim;
                          Bph = Bgh + (size_t)f * HWdim * HWdim; Bpl = Bgl + (size_t)f * HWdim * HWdim; }

    auto issue = [&](int buf, int k0) {
        __nv_bfloat16* Sa_h = sm + buf * STG_H;
        __nv_bfloat16* Sa_l = Sa_h + 5120;
        __nv_bfloat16* Sb_h = Sa_h + 10240;
        __nv_bfloat16* Sb_l = Sa_h + 15360;
        if (MODE == 1) {                       // A: [k][m] -> [32][136]
            int row = tid >> 3, c0 = (tid & 7) * 8;
            const __nv_bfloat16* s0 = Aph + (size_t)(k0 + row) * Ndim + bm;
            const __nv_bfloat16* s1 = Apl + (size_t)(k0 + row) * Ndim + bm;
            CP16(smem_u32(Sa_h + row*136 + c0),      s0 + c0);
            CP16(smem_u32(Sa_h + row*136 + c0 + 64), s0 + c0 + 64);
            CP16(smem_u32(Sa_l + row*136 + c0),      s1 + c0);
            CP16(smem_u32(Sa_l + row*136 + c0 + 64), s1 + c0 + 64);
        } else {                               // A: [m][k] -> [128][40]
            const size_t lda = (MODE == 0) ? (size_t)Cdim : (size_t)Ndim;
            int row = tid >> 1, c0 = (tid & 1) * 8;
            const __nv_bfloat16* s0 = Aph + (size_t)(bm + row) * lda + k0;
            const __nv_bfloat16* s1 = Apl + (size_t)(bm + row) * lda + k0;
            CP16(smem_u32(Sa_h + row*40 + c0),      s0 + c0);
            CP16(smem_u32(Sa_h + row*40 + c0 + 16), s0 + c0 + 16);
            CP16(smem_u32(Sa_l + row*40 + c0),      s1 + c0);
            CP16(smem_u32(Sa_l + row*40 + c0 + 16), s1 + c0 + 16);
        }
        if (MODE == 2) {                       // B: [n][k] -> [128][40]
            int row = tid >> 1, c0 = (tid & 1) * 8;
            const __nv_bfloat16* s0 = Bph + (size_t)(bn + row) * HWdim + k0;
            const __nv_bfloat16* s1 = Bpl + (size_t)(bn + row) * HWdim + k0;
            CP16(smem_u32(Sb_h + row*40 + c0),      s0 + c0);
            CP16(smem_u32(Sb_h + row*40 + c0 + 16), s0 + c0 + 16);
            CP16(smem_u32(Sb_l + row*40 + c0),      s1 + c0);
            CP16(smem_u32(Sb_l + row*40 + c0 + 16), s1 + c0 + 16);
        } else {                               // B: [k][n] -> [32][136]
            int row = tid >> 3, c0 = (tid & 7) * 8;
            const __nv_bfloat16* s0 = Bph + (size_t)(k0 + row) * Ndim + bn;
            const __nv_bfloat16* s1 = Bpl + (size_t)(k0 + row) * Ndim + bn;
            CP16(smem_u32(Sb_h + row*136 + c0),      s0 + c0);
            CP16(smem_u32(Sb_h + row*136 + c0 + 64), s0 + c0 + 64);
            CP16(smem_u32(Sb_l + row*136 + c0),      s1 + c0);
            CP16(smem_u32(Sb_l + row*136 + c0 + 64), s1 + c0 + 64);
        }
    };

    float acc[4][4][4] = {};

    issue(0, 0); CPCOMMIT();

    for (int s = 0; s < NSTG; s++) {
        if (s + 1 < NSTG) { issue((s + 1) & 1, (s + 1) * 32); CPCOMMIT(); CPWAIT(1); }
        else CPWAIT(0);
        __syncthreads();

        const __nv_bfloat16* Sa_h = sm + (s & 1) * STG_H;
        const __nv_bfloat16* Sa_l = Sa_h + 5120;
        const __nv_bfloat16* Sb_h = Sa_h + 10240;
        const __nv_bfloat16* Sb_l = Sa_h + 15360;

#pragma unroll
        for (int k16 = 0; k16 < 32; k16 += 16) {
            uint32_t a[4][4], bh[4][2], bl[4][2];
#pragma unroll
            for (int mi = 0; mi < 4; mi++) {
                if (MODE == 1) {
                    int row = k16 + (lane & 7) + ((lane >> 4) << 3);
                    int col = wm + mi*16 + (((lane >> 3) & 1) << 3);
                    LDMX4T(a[mi][0], a[mi][1], a[mi][2], a[mi][3],
                           smem_u32(Sa_h + row*136 + col));
                } else {
                    LDMX4(a[mi][0], a[mi][1], a[mi][2], a[mi][3],
                          smem_u32(Sa_h + (wm + mi*16 + (lane & 15))*40 + k16 + ((lane >> 4) << 3)));
                }
            }
#pragma unroll
            for (int ni = 0; ni < 4; ni++) {
                if (MODE == 2) {
                    uint32_t ad = smem_u32(Sb_h + (wn + ni*8 + (lane & 7))*40 + k16 + (((lane >> 3) & 1) << 3));
                    LDMX2(bh[ni][0], bh[ni][1], ad);
                    uint32_t ad2 = smem_u32(Sb_l + (wn + ni*8 + (lane & 7))*40 + k16 + (((lane >> 3) & 1) << 3));
                    LDMX2(bl[ni][0], bl[ni][1], ad2);
                } else {
                    uint32_t ad = smem_u32(Sb_h + (k16 + (lane & 15))*136 + wn + ni*8);
                    LDMX2T(bh[ni][0], bh[ni][1], ad);
                    uint32_t ad2 = smem_u32(Sb_l + (k16 + (lane & 15))*136 + wn + ni*8);
                    LDMX2T(bl[ni][0], bl[ni][1], ad2);
                }
            }
#pragma unroll
            for (int mi = 0; mi < 4; mi++)
#pragma unroll
                for (int ni = 0; ni < 4; ni++) {
                    MMA_B16(acc[mi][ni][0], acc[mi][ni][1], acc[mi][ni][2], acc[mi][ni][3],
                            a[mi][0], a[mi][1], a[mi][2], a[mi][3], bh[ni][0], bh[ni][1]);
                    MMA_B16(acc[mi][ni][0], acc[mi][ni][1], acc[mi][ni][2], acc[mi][ni][3],
                            a[mi][0], a[mi][1], a[mi][2], a[mi][3], bl[ni][0], bl[ni][1]);
                }
#pragma unroll
            for (int mi = 0; mi < 4; mi++) {
                if (MODE == 1) {
                    int row = k16 + (lane & 7) + ((lane >> 4) << 3);
                    int col = wm + mi*16 + (((lane >> 3) & 1) << 3);
                    LDMX4T(a[mi][0], a[mi][1], a[mi][2], a[mi][3],
                           smem_u32(Sa_l + row*136 + col));
                } else {
                    LDMX4(a[mi][0], a[mi][1], a[mi][2], a[mi][3],
                          smem_u32(Sa_l + (wm + mi*16 + (lane & 15))*40 + k16 + ((lane >> 4) << 3)));
                }
            }
#pragma unroll
            for (int mi = 0; mi < 4; mi++)
#pragma unroll
                for (int ni = 0; ni < 4; ni++)
                    MMA_B16(acc[mi][ni][0], acc[mi][ni][1], acc[mi][ni][2], acc[mi][ni][3],
                            a[mi][0], a[mi][1], a[mi][2], a[mi][3], bh[ni][0], bh[ni][1]);
        }
        __syncthreads();
    }

    // ---- epilogue ----
    const size_t ldc = (MODE == 1) ? (size_t)HWdim : (size_t)Ndim;
    float* Cpf = 0; __nv_bfloat16 *Cph = 0, *Cpl = 0;
    if (MODE == 1)      Cpf = Cf + (size_t)f * HWdim * HWdim;
    else if (MODE == 2) { Cph = Ch + (size_t)f * HWdim; Cpl = Cl + (size_t)f * HWdim; }
    else if (SPLIT)     { Cph = Ch; Cpl = Cl; }
    else                Cpf = Cf;

    const int r = lane >> 2, cc = (lane & 3) * 2;
#pragma unroll
    for (int mi = 0; mi < 4; mi++) {
        const int row0 = bm + wm + mi*16 + r;
        const int row1 = row0 + 8;
        float bi0 = 0.f, bi1 = 0.f;
        if (MODE == 0) { bi0 = bias[row0]; bi1 = bias[row1]; }
#pragma unroll
        for (int ni = 0; ni < 4; ni++) {
            const int col = bn + wn + ni*8 + cc;
            float v00 = acc[mi][ni][0], v01 = acc[mi][ni][1];
            float v10 = acc[mi][ni][2], v11 = acc[mi][ni][3];
            if (MODE == 0) { v00 += bi0; v01 += bi0; v10 += bi1; v11 += bi1; }
            if (MODE == 1) { v00 *= SCALEv; v01 *= SCALEv; v10 *= SCALEv; v11 *= SCALEv; }
            if (SPLIT) {
                __nv_bfloat16 h0,l0,h1,l1,h2,l2,h3,l3;
                split_bf16(v00,h0,l0); split_bf16(v01,h1,l1);
                split_bf16(v10,h2,l2); split_bf16(v11,h3,l3);
                *(__nv_bfloat162*)(Cph + (size_t)row0*ldc + col) = __nv_bfloat162(h0,h1);
                *(__nv_bfloat162*)(Cpl + (size_t)row0*ldc + col) = __nv_bfloat162(l0,l1);
                *(__nv_bfloat162*)(Cph + (size_t)row1*ldc + col) = __nv_bfloat162(h2,h3);
                *(__nv_bfloat162*)(Cpl + (size_t)row1*ldc + col) = __nv_bfloat162(l2,l3);
            } else {
                if (MODE == 0 && resid) {
                    float2 r0 = *(const float2*)(resid + (size_t)row0*ldc + col);
                    float2 r1 = *(const float2*)(resid + (size_t)row1*ldc + col);
                    v00 += r0.x; v01 += r0.y; v10 += r1.x; v11 += r1.y;
                }
                *(float2*)(Cpf + (size_t)row0*ldc + col) = make_float2(v00, v01);
                *(float2*)(Cpf + (size_t)row1*ldc + col) = make_float2(v10, v11);
            }
        }
    }
}

// ---------------- softmax: fp32 scores -> bf16 hi/lo probs ----------------
__global__ void __launch_bounds__(256)
softmax_kernel() {
    const size_t base = (size_t)blockIdx.x * HWdim;
    const float* row = g_s + base;
    const int tid = threadIdx.x;
    float r[9];
    float mx = -1e30f;
#pragma unroll
    for (int i = 0; i < 9; i++) {
        r[i] = row[tid + i * 256];
        mx = fmaxf(mx, r[i]);
    }
    __shared__ float sh[256];
    sh[tid] = mx;
    __syncthreads();
    for (int off = 128; off > 0; off >>= 1) {
        if (tid < off) sh[tid] = fmaxf(sh[tid], sh[tid + off]);
        __syncthreads();
    }
    mx = sh[0];
    __syncthreads();
    float s = 0.f;
#pragma unroll
    for (int i = 0; i < 9; i++) {
        r[i] = __expf(r[i] - mx);
        s += r[i];
    }
    sh[tid] = s;
    __syncthreads();
    for (int off = 128; off > 0; off >>= 1) {
        if (tid < off) sh[tid] += sh[tid + off];
        __syncthreads();
    }
    const float inv = 1.f / sh[0];
#pragma unroll
    for (int i = 0; i < 9; i++) {
        float p = r[i] * inv;
        __nv_bfloat16 h, l;
        split_bf16(p, h, l);
        g_ph[base + tid + i * 256] = h;
        g_pl[base + tid + i * 256] = l;
    }
}

// ---------------- launch ----------------
extern "C" void kernel_launch(void* const* d_in, const int* in_sizes, int n_in,
                              void* d_out, int out_size) {
    __nv_bfloat16 *p_hnh, *p_hnl, *p_qh, *p_ql, *p_kh, *p_kl, *p_vh, *p_vl, *p_ofh, *p_ofl, *p_ph, *p_pl, *p_wh, *p_wl;
    float* p_s;
    cudaGetSymbolAddress((void**)&p_hnh, g_hnh); cudaGetSymbolAddress((void**)&p_hnl, g_hnl);
    cudaGetSymbolAddress((void**)&p_qh,  g_qh);  cudaGetSymbolAddress((void**)&p_ql,  g_ql);
    cudaGetSymbolAddress((void**)&p_kh,  g_kh);  cudaGetSymbolAddress((void**)&p_kl,  g_kl);
    cudaGetSymbolAddress((void**)&p_vh,  g_vh);  cudaGetSymbolAddress((void**)&p_vl,  g_vl);
    cudaGetSymbolAddress((void**)&p_ofh, g_ofh); cudaGetSymbolAddress((void**)&p_ofl, g_ofl);
    cudaGetSymbolAddress((void**)&p_ph,  g_ph);  cudaGetSymbolAddress((void**)&p_pl,  g_pl);
    cudaGetSymbolAddress((void**)&p_wh,  g_wh);  cudaGetSymbolAddress((void**)&p_wl,  g_wl);
    cudaGetSymbolAddress((void**)&p_s,   g_s);

    static bool attr_done = false;
    if (!attr_done) {
        cudaFuncSetAttribute(mma_gemm<0,true >, cudaFuncAttributeMaxDynamicSharedMemorySize, SMEMB);
        cudaFuncSetAttribute(mma_gemm<0,false>, cudaFuncAttributeMaxDynamicSharedMemorySize, SMEMB);
        cudaFuncSetAttribute(mma_gemm<1,false>, cudaFuncAttributeMaxDynamicSharedMemorySize, SMEMB);
        cudaFuncSetAttribute(mma_gemm<2,true >, cudaFuncAttributeMaxDynamicSharedMemorySize, SMEMB);
        attr_done = true;
    }

    const float* x     = (const float*)d_in[0];
    const float* gamma = (const float*)d_in[1];
    const float* beta  = (const float*)d_in[2];
    const float* wq    = (const float*)d_in[3];
    const float* bq    = (const float*)d_in[4];
    const float* wk    = (const float*)d_in[5];
    const float* bk    = (const float*)d_in[6];
    const float* wv    = (const float*)d_in[7];
    const float* bv    = (const float*)d_in[8];
    const float* wo    = (const float*)d_in[9];
    const float* bo    = (const float*)d_in[10];
    float* out = (float*)d_out;

    // 0. split all weights (one launch)
    dim3 gW(WSZ / 1024, 1, 4);
    splitw_kernel<<<gW, 256>>>(wq, wk, wv, wo);

    // 1. GroupNorm -> split hn
    gn_stats_kernel<<<Gdim, 1024>>>(x);
    gn_apply_kernel<<<(int)(CN / 4) / 256, 256>>>(x, gamma, beta);

    // 2. Q/K/V projections (separate launches — merged grid.z regressed in R7)
    dim3 gProj(Ndim / 128, Cdim / 128);
    mma_gemm<0,true><<<gProj, 256, SMEMB>>>(p_wh + 0*WSZ, p_wl + 0*WSZ, p_hnh, p_hnl, bq, 0, 0, p_qh, p_ql);
    mma_gemm<0,true><<<gProj, 256, SMEMB>>>(p_wh + 1*WSZ, p_wl + 1*WSZ, p_hnh, p_hnl, bk, 0, 0, p_kh, p_kl);
    mma_gemm<0,true><<<gProj, 256, SMEMB>>>(p_wh + 2*WSZ, p_wl + 2*WSZ, p_hnh, p_hnl, bv, 0, 0, p_vh, p_vl);

    // 3. scores
    dim3 gSc(HWdim / 128, HWdim / 128, Tdim);
    mma_gemm<1,false><<<gSc, 256, SMEMB>>>(p_qh, p_ql, p_kh, p_kl, 0, 0, p_s, 0, 0);

    // 4. softmax -> split probs
    softmax_kernel<<<Tdim * HWdim, 256>>>();

    // 5. PV (split of)
    dim3 gPV(HWdim / 128, Cdim / 128, Tdim);
    mma_gemm<2,true><<<gPV, 256, SMEMB>>>(p_vh, p_vl, p_ph, p_pl, 0, 0, 0, p_ofh, p_ofl);

    // 6. output projection + bias + residual
    mma_gemm<0,false><<<gProj, 256, SMEMB>>>(p_wh + 3*WSZ, p_wl + 3*WSZ, p_ofh, p_ofl, bo, x, out, 0, 0);
}